// round 14
// baseline (speedup 1.0000x reference)
#include <cuda_runtime.h>
#include <cuda_bf16.h>
#include <mma.h>
#include <cstdint>

using namespace nvcuda;

// ============================================================================
// Grouped GEMM (MoE ragged splits), GB300 — fp32-materialized tensors (the
// harness upcasts jax bf16 to fp32; values are exactly bf16-representable).
//
//   out[r,:] = bf16round( x[r,:] @ w[g(r)] ),  IN=256, OUT=128 (fp32 I/O)
//   splits all % 128 == 0  ->  one expert per 128-row tile
//
// R13 passed at 1490us but profiled regs=255 / occ=12.5% (spills + 1 CTA/SM).
// R14: 512 thr = 16 warps (4M x 4N, warp tile 32x32 -> 4 accum frags = 32
// regs), 2-stage cp.async ring (70.7KB smem -> 2 CTAs/SM, 50% occ). tf32
// wmma m16n16k8 (exact on bf16-valued fp32), fp32 accum, bf16-round epilogue.
// ============================================================================

#define A_PITCH_F 36                    // fp32 per smem A row (144 B)
#define B_PITCH_F 132                   // fp32 per smem B row (528 B)
#define SA_BYTES  (128u * 144u)         // 18432
#define SB_BYTES  (32u * 528u)          // 16896
#define STAGE     (SA_BYTES + SB_BYTES) // 35328
#define SMEM_BYTES (2u * STAGE)         // 70656  -> 2 CTAs/SM

// ---------------------------------------------------------------- helpers ---
static __device__ __forceinline__ void cp16(uint32_t dst, const void* src) {
    asm volatile("cp.async.cg.shared.global [%0], [%1], 16;"
                 :: "r"(dst), "l"(src) : "memory");
}
static __device__ __forceinline__ void cp_commit() {
    asm volatile("cp.async.commit_group;" ::: "memory");
}
#define CP_WAIT(n) asm volatile("cp.async.wait_group %0;" :: "n"(n) : "memory")

static __device__ __forceinline__ uint32_t smem_u32(const void* p) {
    uint32_t a;
    asm("{ .reg .u64 t; cvta.to.shared.u64 t, %1; cvt.u32.u64 %0, t; }"
        : "=r"(a) : "l"(p));
    return a;
}

// ------------------------------------------------------------- stage loads ---
// A chunk: x tile rows [0,128) x k [kc*32, kc*32+32) fp32  (128 x 8 16B ops)
// B chunk: w[g] k rows [kc*32, kc*32+32) x n [0,128) fp32  (32 x 32 16B ops)
static __device__ __forceinline__ void load_chunk(
    const float* __restrict__ xb, const float* __restrict__ wb,
    int kc, uint32_t stage_base, int tid) {
    uint32_t sA = stage_base;
    uint32_t sB = stage_base + SA_BYTES;
#pragma unroll
    for (int j = 0; j < 2; ++j) {
        int idx = tid + j * 512;                 // 0..1023
        int ra = idx >> 3, ca = idx & 7;
        cp16(sA + (uint32_t)ra * 144u + (uint32_t)(ca << 4),
             xb + (size_t)ra * 256 + kc * 32 + ca * 4);
        int rb = idx >> 5, cb = idx & 31;
        cp16(sB + (uint32_t)rb * 528u + (uint32_t)(cb << 4),
             wb + (size_t)(kc * 32 + rb) * 128 + cb * 4);
    }
    cp_commit();
}

// --------------------------------------------------------------- compute ----
using FragA = wmma::fragment<wmma::matrix_a, 16, 16, 8,
                             wmma::precision::tf32, wmma::row_major>;
using FragB = wmma::fragment<wmma::matrix_b, 16, 16, 8,
                             wmma::precision::tf32, wmma::row_major>;
using FragC = wmma::fragment<wmma::accumulator, 16, 16, 8, float>;

static __device__ __forceinline__ void compute_chunk(
    const char* st, FragC cfr[2][2], int wm, int wn) {
    const float* sA = (const float*)st;
    const float* sB = (const float*)(st + SA_BYTES);
#pragma unroll
    for (int ks = 0; ks < 4; ++ks) {
        int kk = ks * 8;
        FragA a[2];
#pragma unroll
        for (int m = 0; m < 2; ++m) {
            wmma::load_matrix_sync(a[m],
                sA + (size_t)(wm + m * 16) * A_PITCH_F + kk, A_PITCH_F);
#pragma unroll
            for (int t = 0; t < a[m].num_elements; ++t)
                a[m].x[t] = wmma::__float_to_tf32(a[m].x[t]);
        }
#pragma unroll
        for (int n = 0; n < 2; ++n) {
            FragB b;
            wmma::load_matrix_sync(b,
                sB + (size_t)kk * B_PITCH_F + wn + n * 16, B_PITCH_F);
#pragma unroll
            for (int t = 0; t < b.num_elements; ++t)
                b.x[t] = wmma::__float_to_tf32(b.x[t]);
#pragma unroll
            for (int m = 0; m < 2; ++m)
                wmma::mma_sync(cfr[m][n], a[m], b, cfr[m][n]);
        }
    }
}

// ----------------------------------------------------------------- kernel ---
__global__ void __launch_bounds__(512, 2) gg_kernel(
    const float* __restrict__ x,
    const float* __restrict__ w,
    const int* __restrict__ gsizes,
    float* __restrict__ out,
    int n_groups) {
    extern __shared__ char smem[];
    int tid = threadIdx.x;
    int wid = tid >> 5;
    int tile = blockIdx.x;

    // expert owning this tile (splits % 128 == 0 -> exact tile boundaries)
    int g = n_groups - 1;
    {
        int acc = 0;
        for (int i = 0; i < n_groups; ++i) {
            acc += gsizes[i] >> 7;
            if (tile < acc) { g = i; break; }
        }
    }

    const float* xb = x + (size_t)tile * 128 * 256;
    const float* wb = w + (size_t)g * 256 * 128;
    uint32_t sb = smem_u32(smem);

    // prologue: chunks 0,1 into the two ring stages
    load_chunk(xb, wb, 0, sb + 0 * STAGE, tid);
    load_chunk(xb, wb, 1, sb + 1 * STAGE, tid);

    int wm = (wid & 3) << 5;          // warp M offset: 0/32/64/96
    int wn = (wid >> 2) << 5;         // warp N offset: 0/32/64/96

    FragC cfr[2][2];
#pragma unroll
    for (int m = 0; m < 2; ++m)
#pragma unroll
        for (int n = 0; n < 2; ++n)
            wmma::fill_fragment(cfr[m][n], 0.0f);

#pragma unroll
    for (int i = 0; i < 8; ++i) {
        if (i < 7) { CP_WAIT(1); } else { CP_WAIT(0); }
        __syncthreads();
        compute_chunk(smem + (size_t)(i & 1) * STAGE, cfr, wm, wn);
        if (i + 2 < 8) {
            __syncthreads();          // stage (i&1) fully consumed
            load_chunk(xb, wb, i + 2, sb + (uint32_t)(i & 1) * STAGE, tid);
        }
    }

    // epilogue: round to bf16 (reference is bf16-rounded), store fp32 direct
    float* ob = out + (size_t)tile * 128 * 128;
#pragma unroll
    for (int m = 0; m < 2; ++m)
#pragma unroll
        for (int n = 0; n < 2; ++n) {
#pragma unroll
            for (int t = 0; t < cfr[m][n].num_elements; ++t)
                cfr[m][n].x[t] =
                    __bfloat162float(__float2bfloat16(cfr[m][n].x[t]));
            wmma::store_matrix_sync(
                ob + (size_t)(wm + m * 16) * 128 + wn + n * 16,
                cfr[m][n], 128, wmma::mem_row_major);
        }
}

// -------------------------------------------------------------------- host ---
extern "C" void kernel_launch(void* const* d_in, const int* in_sizes, int n_in,
                              void* d_out, int out_size) {
    // identify inputs by element count (x=max, group_sizes=min, w=rest)
    int ix = 0, ig = 0;
    for (int i = 1; i < n_in; ++i) {
        if (in_sizes[i] > in_sizes[ix]) ix = i;
        if (in_sizes[i] < in_sizes[ig]) ig = i;
    }
    int iw = 0;
    for (int i = 0; i < n_in; ++i)
        if (i != ix && i != ig) { iw = i; break; }

    const float* x  = (const float*)d_in[ix];      // fp32 (bf16-valued)
    const float* w  = (const float*)d_in[iw];      // fp32 (bf16-valued)
    const int*   gs = (const int*)d_in[ig];
    float*      out = (float*)d_out;               // fp32 output

    int n_groups = in_sizes[ig];
    if (n_groups > 64) n_groups = 64;
    int n_tiles = in_sizes[ix] / (256 * 128);

    cudaFuncSetAttribute(gg_kernel, cudaFuncAttributeMaxDynamicSharedMemorySize,
                         (int)SMEM_BYTES);
    gg_kernel<<<n_tiles, 512, SMEM_BYTES>>>(x, w, gs, out, n_groups);
}

// round 15
// speedup vs baseline: 5.4062x; 5.4062x over previous
#include <cuda_runtime.h>
#include <cuda_bf16.h>
#include <mma.h>
#include <cstdint>

using namespace nvcuda;

// ============================================================================
// Grouped GEMM (MoE ragged splits), GB300 — fp32-materialized tensors (values
// exactly bf16-representable; reference output is bf16-rounded then upcast).
//
//   out[r,:] = bf16round( x[r,:] @ w[g(r)] ),  IN=256, OUT=128 (fp32 I/O)
//   splits all % 128 == 0  ->  one expert per 128-row tile
//
// R14 lesson (ncu): K-chunked staging reads 128B-per-1KB-stride -> DRAM
// activate-bound (75% dram busy at 2x duration). R15 streams M instead:
// each stage = 32 FULL x rows (32KB contiguous), register-staged double
// buffer; w[g] converted once to bf16 smem (L2-resident source); native
// bf16 wmma m16n16k16; 101KB smem -> 2 CTAs/SM; 16 warps = 2M x 8N.
// ============================================================================

#define BP 136                       // B smem pitch, bf16 elems (272 B)
#define AP 264                       // A smem pitch, bf16 elems (528 B)
#define SB_ELEMS (256 * BP)          // 34816 bf16 = 69632 B
#define SA_ELEMS (32 * AP)           // 8448 bf16 = 16896 B per buffer
#define SMEM_BYTES (SB_ELEMS * 2 + 2 * SA_ELEMS * 2)   // 103424

static __device__ __forceinline__ uint32_t pack_bf(float f0, float f1) {
    return (uint32_t)__bfloat16_as_ushort(__float2bfloat16(f0)) |
           ((uint32_t)__bfloat16_as_ushort(__float2bfloat16(f1)) << 16);
}

using FragA = wmma::fragment<wmma::matrix_a, 16, 16, 16, __nv_bfloat16,
                             wmma::row_major>;
using FragB = wmma::fragment<wmma::matrix_b, 16, 16, 16, __nv_bfloat16,
                             wmma::row_major>;
using FragC = wmma::fragment<wmma::accumulator, 16, 16, 16, float>;

// ----------------------------------------------------------------- kernel ---
__global__ void __launch_bounds__(512, 2) gg_kernel(
    const float* __restrict__ x,
    const float* __restrict__ w,
    const int* __restrict__ gsizes,
    float* __restrict__ out,
    int n_groups) {
    extern __shared__ char smem[];
    __nv_bfloat16* sB = (__nv_bfloat16*)smem;                 // [256][BP]
    __nv_bfloat16* sA = (__nv_bfloat16*)(smem + SB_ELEMS * 2); // [2][32][AP]

    int tid = threadIdx.x;
    int wid = tid >> 5;
    int tile = blockIdx.x;

    // expert owning this tile (splits % 128 == 0 -> exact tile boundaries)
    int g = n_groups - 1;
    {
        int acc = 0;
        for (int i = 0; i < n_groups; ++i) {
            acc += gsizes[i] >> 7;
            if (tile < acc) { g = i; break; }
        }
    }

    const float* xb = x + (size_t)tile * 128 * 256;
    const float* wb = w + (size_t)g * 256 * 128;
    float* ob = out + (size_t)tile * 128 * 128;

    // ---- load B (w[g], 128KB fp32, L2-resident) -> bf16 smem, once ----
#pragma unroll 4
    for (int j = 0; j < 16; ++j) {
        int u = tid + j * 512;            // 0..8191 uint4 units
        int row = u >> 5, col = u & 31;   // 32 uint4 per 128-float row
        float4 v = *(const float4*)(wb + (size_t)row * 128 + col * 4);
        *(uint2*)(sB + row * BP + col * 4) =
            make_uint2(pack_bf(v.x, v.y), pack_bf(v.z, v.w));
    }

    // ---- prologue: A stage 0 (rows 0..31, full K) via registers ----
    float4 ar[4];
#pragma unroll
    for (int j = 0; j < 4; ++j) {
        int u = tid + j * 512;            // 0..2047 uint4 units
        int row = u >> 6, col = u & 63;   // 64 uint4 per 256-float row
        ar[j] = *(const float4*)(xb + (size_t)row * 256 + col * 4);
    }
#pragma unroll
    for (int j = 0; j < 4; ++j) {
        int u = tid + j * 512;
        int row = u >> 6, col = u & 63;
        *(uint2*)(sA + row * AP + col * 4) =
            make_uint2(pack_bf(ar[j].x, ar[j].y), pack_bf(ar[j].z, ar[j].w));
    }
    __syncthreads();

    int wmSub = (wid & 1) << 4;           // 0/16 within the 32-row stage
    int wn    = (wid >> 1) << 4;          // 0..112 N offset

    // ---- 4 stages of 32 rows ----
#pragma unroll
    for (int s = 0; s < 4; ++s) {
        int buf = s & 1;
        // prefetch next stage's rows into registers (contiguous 32KB span)
        if (s < 3) {
            const float* xs = xb + (size_t)(s + 1) * 32 * 256;
#pragma unroll
            for (int j = 0; j < 4; ++j) {
                int u = tid + j * 512;
                int row = u >> 6, col = u & 63;
                ar[j] = *(const float4*)(xs + (size_t)row * 256 + col * 4);
            }
        }

        // compute 32x128 output block from sA[buf] x sB
        FragC acc;
        wmma::fill_fragment(acc, 0.0f);
        const __nv_bfloat16* Ab = sA + buf * SA_ELEMS + wmSub * AP;
#pragma unroll
        for (int ks = 0; ks < 16; ++ks) {
            FragA fa;
            FragB fb;
            wmma::load_matrix_sync(fa, Ab + ks * 16, AP);
            wmma::load_matrix_sync(fb, sB + ks * 16 * BP + wn, BP);
            wmma::mma_sync(acc, fa, fb, acc);
        }
        // bf16-round (reference rounds to bf16) and store fp32
#pragma unroll
        for (int t = 0; t < acc.num_elements; ++t)
            acc.x[t] = __bfloat162float(__float2bfloat16(acc.x[t]));
        wmma::store_matrix_sync(ob + (size_t)(s * 32 + wmSub) * 128 + wn,
                                acc, 128, wmma::mem_row_major);

        __syncthreads();                  // all reads of sA[buf^1] (s-1) done
        if (s < 3) {
#pragma unroll
            for (int j = 0; j < 4; ++j) {
                int u = tid + j * 512;
                int row = u >> 6, col = u & 63;
                *(uint2*)(sA + (buf ^ 1) * SA_ELEMS + row * AP + col * 4) =
                    make_uint2(pack_bf(ar[j].x, ar[j].y),
                               pack_bf(ar[j].z, ar[j].w));
            }
            __syncthreads();              // stage s+1 visible
        }
    }
}

// -------------------------------------------------------------------- host ---
extern "C" void kernel_launch(void* const* d_in, const int* in_sizes, int n_in,
                              void* d_out, int out_size) {
    // identify inputs by element count (x=max, group_sizes=min, w=rest)
    int ix = 0, ig = 0;
    for (int i = 1; i < n_in; ++i) {
        if (in_sizes[i] > in_sizes[ix]) ix = i;
        if (in_sizes[i] < in_sizes[ig]) ig = i;
    }
    int iw = 0;
    for (int i = 0; i < n_in; ++i)
        if (i != ix && i != ig) { iw = i; break; }

    const float* x  = (const float*)d_in[ix];      // fp32 (bf16-valued)
    const float* w  = (const float*)d_in[iw];      // fp32 (bf16-valued)
    const int*   gs = (const int*)d_in[ig];
    float*      out = (float*)d_out;               // fp32 output

    int n_groups = in_sizes[ig];
    if (n_groups > 64) n_groups = 64;
    int n_tiles = in_sizes[ix] / (256 * 128);

    cudaFuncSetAttribute(gg_kernel, cudaFuncAttributeMaxDynamicSharedMemorySize,
                         (int)SMEM_BYTES);
    gg_kernel<<<n_tiles, 512, SMEM_BYTES>>>(x, w, gs, out, n_groups);
}

// round 16
// speedup vs baseline: 6.7510x; 1.2487x over previous
#include <cuda_runtime.h>
#include <cuda_bf16.h>
#include <mma.h>
#include <cstdint>

using namespace nvcuda;

// ============================================================================
// Grouped GEMM (MoE ragged splits), GB300 — fp32-materialized tensors (values
// exactly bf16-representable; reference output is bf16-rounded then upcast).
//
//   out[r,:] = bf16round( x[r,:] @ w[g(r)] ),  IN=256, OUT=128 (fp32 I/O)
//   splits all % 128 == 0  ->  one expert per 128-row tile
//
// R15 (539us) profiled L1=71.7% / tensor=15.7%: 16x16 warp tile moves 1KB of
// LDS per mma + conflicting pitches. R16: 32x32 warp tile (0.5KB/mma, 2x LDS
// cut), pitches == 48 mod 128B (conflict-free ldmatrix rows), 256thr x
// 2 CTAs/SM, 64-row contiguous A stages with 2-wave register prefetch.
// ============================================================================

#define BP 152                        // B smem pitch, bf16 elems (304 B % 128 = 48)
#define AP 280                        // A smem pitch, bf16 elems (560 B % 128 = 48)
#define SB_ELEMS (256 * BP)           // 38912 bf16 = 77824 B
#define SA_ELEMS (64 * AP)            // 17920 bf16 = 35840 B
#define SMEM_BYTES ((SB_ELEMS + SA_ELEMS) * 2)   // 113664 -> 2 CTAs/SM

static __device__ __forceinline__ uint32_t pack_bf(float f0, float f1) {
    return (uint32_t)__bfloat16_as_ushort(__float2bfloat16(f0)) |
           ((uint32_t)__bfloat16_as_ushort(__float2bfloat16(f1)) << 16);
}

using FragA = wmma::fragment<wmma::matrix_a, 16, 16, 16, __nv_bfloat16,
                             wmma::row_major>;
using FragB = wmma::fragment<wmma::matrix_b, 16, 16, 16, __nv_bfloat16,
                             wmma::row_major>;
using FragC = wmma::fragment<wmma::accumulator, 16, 16, 16, float>;

// one k-step: 2 A frags + 2 B frags -> 4 mma  (warp tile 32x32)
static __device__ __forceinline__ void kstep(
    const __nv_bfloat16* sA, const __nv_bfloat16* sB,
    FragC acc[2][2], int wm, int wn, int ks) {
    FragA fa[2];
    FragB fb[2];
#pragma unroll
    for (int m = 0; m < 2; ++m)
        wmma::load_matrix_sync(fa[m], sA + (size_t)(wm + m * 16) * AP + ks * 16,
                               AP);
#pragma unroll
    for (int n = 0; n < 2; ++n)
        wmma::load_matrix_sync(fb[n], sB + (size_t)ks * 16 * BP + wn + n * 16,
                               BP);
#pragma unroll
    for (int m = 0; m < 2; ++m)
#pragma unroll
        for (int n = 0; n < 2; ++n)
            wmma::mma_sync(acc[m][n], fa[m], fb[n], acc[m][n]);
}

// ----------------------------------------------------------------- kernel ---
__global__ void __launch_bounds__(256, 2) gg_kernel(
    const float* __restrict__ x,
    const float* __restrict__ w,
    const int* __restrict__ gsizes,
    float* __restrict__ out,
    int n_groups) {
    extern __shared__ char smem[];
    __nv_bfloat16* sB = (__nv_bfloat16*)smem;              // [256][BP]
    __nv_bfloat16* sA = (__nv_bfloat16*)(smem + SB_ELEMS * 2);  // [64][AP]

    int tid = threadIdx.x;
    int wid = tid >> 5;
    int tile = blockIdx.x;

    // expert owning this tile (splits % 128 == 0 -> exact tile boundaries)
    int g = n_groups - 1;
    {
        int acc = 0;
        for (int i = 0; i < n_groups; ++i) {
            acc += gsizes[i] >> 7;
            if (tile < acc) { g = i; break; }
        }
    }

    const float* xb = x + (size_t)tile * 128 * 256;
    const float* wb = w + (size_t)g * 256 * 128;
    float* ob = out + (size_t)tile * 128 * 128;

    // ---- B (w[g], L2-resident) -> bf16 smem, once; warp reads 1 row (512B) ----
#pragma unroll 4
    for (int j = 0; j < 32; ++j) {
        int u = tid + j * 256;            // 0..8191 float4 units
        int row = u >> 5, c4 = u & 31;    // 32 float4 per 128-float row
        float4 v = *(const float4*)(wb + (size_t)row * 128 + c4 * 4);
        *(uint2*)(sB + (size_t)row * BP + c4 * 4) =
            make_uint2(pack_bf(v.x, v.y), pack_bf(v.z, v.w));
    }

    // ---- A stage 0 (rows 0..63, full K): ld -> pack -> sts ----
#pragma unroll 4
    for (int j = 0; j < 16; ++j) {
        int u = tid + j * 256;            // 0..4095
        int row = u >> 6, c4 = u & 63;    // 64 float4 per 256-float row
        float4 v = *(const float4*)(xb + (size_t)row * 256 + c4 * 4);
        *(uint2*)(sA + (size_t)row * AP + c4 * 4) =
            make_uint2(pack_bf(v.x, v.y), pack_bf(v.z, v.w));
    }
    __syncthreads();

    int wm = (wid & 1) << 5;              // 0/32 (rows within 64-row stage)
    int wn = (wid >> 1) << 5;             // 0/32/64/96 (N offset)
    const float* xs = xb + 64 * 256;      // stage-1 source rows

    FragC acc[2][2];
    float4 p1[8], p2[8];

#pragma unroll
    for (int s = 0; s < 2; ++s) {
#pragma unroll
        for (int m = 0; m < 2; ++m)
#pragma unroll
            for (int n = 0; n < 2; ++n)
                wmma::fill_fragment(acc[m][n], 0.0f);

        // prefetch wave 1 (stage-1 rows 64..95) overlapping first k-half
        if (s == 0) {
#pragma unroll
            for (int j = 0; j < 8; ++j) {
                int u = tid + j * 256;
                int row = u >> 6, c4 = u & 63;
                p1[j] = *(const float4*)(xs + (size_t)row * 256 + c4 * 4);
            }
        }
#pragma unroll
        for (int ks = 0; ks < 8; ++ks) kstep(sA, sB, acc, wm, wn, ks);

        if (s == 0) {
#pragma unroll
            for (int j = 0; j < 8; ++j) {
                int u = tid + (j + 8) * 256;
                int row = u >> 6, c4 = u & 63;
                p2[j] = *(const float4*)(xs + (size_t)row * 256 + c4 * 4);
            }
        }
#pragma unroll
        for (int ks = 8; ks < 16; ++ks) kstep(sA, sB, acc, wm, wn, ks);

        // epilogue: bf16-round (reference rounds to bf16), store fp32
#pragma unroll
        for (int m = 0; m < 2; ++m)
#pragma unroll
            for (int n = 0; n < 2; ++n) {
#pragma unroll
                for (int t = 0; t < acc[m][n].num_elements; ++t)
                    acc[m][n].x[t] =
                        __bfloat162float(__float2bfloat16(acc[m][n].x[t]));
                wmma::store_matrix_sync(
                    ob + (size_t)(s * 64 + wm + m * 16) * 128 + wn + n * 16,
                    acc[m][n], 128, wmma::mem_row_major);
            }

        // swap in stage 1
        if (s == 0) {
            __syncthreads();              // all warps done reading sA stage 0
#pragma unroll
            for (int j = 0; j < 8; ++j) {
                int u = tid + j * 256;
                int row = u >> 6, c4 = u & 63;
                *(uint2*)(sA + (size_t)row * AP + c4 * 4) =
                    make_uint2(pack_bf(p1[j].x, p1[j].y),
                               pack_bf(p1[j].z, p1[j].w));
            }
#pragma unroll
            for (int j = 0; j < 8; ++j) {
                int u = tid + (j + 8) * 256;
                int row = u >> 6, c4 = u & 63;
                *(uint2*)(sA + (size_t)row * AP + c4 * 4) =
                    make_uint2(pack_bf(p2[j].x, p2[j].y),
                               pack_bf(p2[j].z, p2[j].w));
            }
            __syncthreads();              // stage 1 visible
        }
    }
}

// -------------------------------------------------------------------- host ---
extern "C" void kernel_launch(void* const* d_in, const int* in_sizes, int n_in,
                              void* d_out, int out_size) {
    // identify inputs by element count (x=max, group_sizes=min, w=rest)
    int ix = 0, ig = 0;
    for (int i = 1; i < n_in; ++i) {
        if (in_sizes[i] > in_sizes[ix]) ix = i;
        if (in_sizes[i] < in_sizes[ig]) ig = i;
    }
    int iw = 0;
    for (int i = 0; i < n_in; ++i)
        if (i != ix && i != ig) { iw = i; break; }

    const float* x  = (const float*)d_in[ix];      // fp32 (bf16-valued)
    const float* w  = (const float*)d_in[iw];      // fp32 (bf16-valued)
    const int*   gs = (const int*)d_in[ig];
    float*      out = (float*)d_out;               // fp32 output

    int n_groups = in_sizes[ig];
    if (n_groups > 64) n_groups = 64;
    int n_tiles = in_sizes[ix] / (256 * 128);

    cudaFuncSetAttribute(gg_kernel, cudaFuncAttributeMaxDynamicSharedMemorySize,
                         (int)SMEM_BYTES);
    gg_kernel<<<n_tiles, 256, SMEM_BYTES>>>(x, w, gs, out, n_groups);
}

// round 17
// speedup vs baseline: 11.6020x; 1.7186x over previous
#include <cuda_runtime.h>
#include <cuda_bf16.h>
#include <cstdint>

// ============================================================================
// Grouped GEMM (MoE ragged splits), GB300 — fp32-materialized tensors (values
// exactly bf16-representable; reference output is bf16-rounded then upcast).
//
//   out[r,:] = bf16round( x[r,:] @ w[g(r)] ),  IN=256, OUT=128 (fp32 I/O)
//   splits all % 128 == 0  ->  one expert per 128-row tile
//
// R16 (432us): latency-bound (occ 24%, no pipe >60%). R17: B leaves smem
// entirely — prologue repacks w into fragment-major global g_wfrag (L2-
// resident, 512KB); B frags load via one LDG.64 per n8 block directly to
// registers. A-only smem (35.8KB) -> 3 CTAs/SM. Hand mma.sync.m16n8k16 bf16
// (layouts validated by R4/R5==R6 forensics), warp tile 32x32, ldmatrix.x4
// non-trans A from conflict-free 560B-pitch smem.
// ============================================================================

#define AP_BYTES 560u                    // A smem row pitch (mod 128 = 48)
#define SMEM_BYTES (64u * AP_BYTES)      // 35840 -> 3 CTAs/SM

__device__ uint2 g_wfrag[8 * 16 * 16 * 32];   // [g][nb][ks][lane], 512 KB

static __device__ __forceinline__ uint32_t pack_bf(float f0, float f1) {
    return (uint32_t)__bfloat16_as_ushort(__float2bfloat16(f0)) |
           ((uint32_t)__bfloat16_as_ushort(__float2bfloat16(f1)) << 16);
}
static __device__ __forceinline__ uint32_t smem_u32(const void* p) {
    uint32_t a;
    asm("{ .reg .u64 t; cvta.to.shared.u64 t, %1; cvt.u32.u64 %0, t; }"
        : "=r"(a) : "l"(p));
    return a;
}
static __device__ __forceinline__ void ldsm_x4(uint32_t* r, uint32_t addr) {
    asm volatile("ldmatrix.sync.aligned.m8n8.x4.shared.b16 {%0,%1,%2,%3}, [%4];"
                 : "=r"(r[0]), "=r"(r[1]), "=r"(r[2]), "=r"(r[3]) : "r"(addr));
}
static __device__ __forceinline__ void mma_bf16(float* c, const uint32_t* a,
                                                uint32_t b0, uint32_t b1) {
    asm volatile(
        "mma.sync.aligned.m16n8k16.row.col.f32.bf16.bf16.f32 "
        "{%0,%1,%2,%3}, {%4,%5,%6,%7}, {%8,%9}, {%0,%1,%2,%3};"
        : "+f"(c[0]), "+f"(c[1]), "+f"(c[2]), "+f"(c[3])
        : "r"(a[0]), "r"(a[1]), "r"(a[2]), "r"(a[3]), "r"(b0), "r"(b1));
}

// --------------------------------------------------------- weight repack ----
// w[g][k=256][n=128] fp32 -> g_wfrag[((g*16+nb)*16+ks)*32+lane] = {b0,b1}
// m16n8k16 col-B fragment: n = nb*8 + lane/4, k = ks*16 + 2*(lane%4);
//   b0 = {B[k][n], B[k+1][n]},  b1 = {B[k+8][n], B[k+9][n]}
__global__ void prep_w(const float* __restrict__ w, int n_groups) {
    int t = blockIdx.x * blockDim.x + threadIdx.x;
    if (t >= n_groups * 8192) return;
    int g = t >> 13, r = t & 8191;
    int nb = r >> 9, r2 = r & 511;
    int ks = r2 >> 5, lane = r2 & 31;
    int n = nb * 8 + (lane >> 2);
    int k = ks * 16 + 2 * (lane & 3);
    const float* wg = w + (size_t)g * 32768;
    uint32_t b0 = pack_bf(wg[(size_t)k * 128 + n], wg[(size_t)(k + 1) * 128 + n]);
    uint32_t b1 = pack_bf(wg[(size_t)(k + 8) * 128 + n],
                          wg[(size_t)(k + 9) * 128 + n]);
    g_wfrag[t] = make_uint2(b0, b1);
}

// ----------------------------------------------------------------- kernel ---
__global__ void __launch_bounds__(256, 3) gg_kernel(
    const float* __restrict__ x,
    const int* __restrict__ gsizes,
    float* __restrict__ out,
    int n_groups) {
    extern __shared__ char smem[];          // A: [64 rows][560 B]
    int tid = threadIdx.x;
    int lane = tid & 31;
    int wid = tid >> 5;
    int tile = blockIdx.x;

    // expert owning this tile (splits % 128 == 0 -> exact tile boundaries)
    int g = n_groups - 1;
    {
        int acc = 0;
        for (int i = 0; i < n_groups; ++i) {
            acc += gsizes[i] >> 7;
            if (tile < acc) { g = i; break; }
        }
    }

    const float* xb = x + (size_t)tile * 128 * 256;
    float* ob = out + (size_t)tile * 128 * 128;
    uint32_t sA = smem_u32(smem);

    int wm = (wid & 1) << 5;                // 0/32 within 64-row stage
    int wn = (wid >> 1) << 5;               // 0/32/64/96 N offset
    const uint2* wf = g_wfrag + ((size_t)g * 16 + (wn >> 3)) * 512 + lane;
    // wf + i*512 + ks*32  ->  fragment for n8-block (wn/8 + i), k-step ks

    // ldmatrix lane address components (A 16x16 frags, non-trans)
    uint32_t arow = (uint32_t)(lane & 15) * AP_BYTES + (uint32_t)(lane >> 4) * 16u;

    // ---- fill A stage 0 (rows 0..63, full K) ----
#pragma unroll 4
    for (int j = 0; j < 16; ++j) {
        int u = tid + j * 256;              // 0..4095
        int row = u >> 6, c4 = u & 63;      // 64 float4 per 256-float row
        float4 v = *(const float4*)(xb + (size_t)row * 256 + c4 * 4);
        *(uint2*)(smem + (size_t)row * AP_BYTES + c4 * 8) =
            make_uint2(pack_bf(v.x, v.y), pack_bf(v.z, v.w));
    }
    __syncthreads();

#pragma unroll
    for (int s = 0; s < 2; ++s) {
        float acc[2][4][4];
#pragma unroll
        for (int m = 0; m < 2; ++m)
#pragma unroll
            for (int n = 0; n < 4; ++n)
#pragma unroll
                for (int t2 = 0; t2 < 4; ++t2) acc[m][n][t2] = 0.0f;

#pragma unroll
        for (int ks = 0; ks < 16; ++ks) {
            uint32_t a[2][4];
            uint32_t abase = sA + (uint32_t)wm * AP_BYTES + arow +
                             (uint32_t)ks * 32u;
            ldsm_x4(a[0], abase);
            ldsm_x4(a[1], abase + 16u * AP_BYTES);
            uint2 b[4];
#pragma unroll
            for (int i = 0; i < 4; ++i) b[i] = __ldg(wf + i * 512 + ks * 32);
#pragma unroll
            for (int m = 0; m < 2; ++m)
#pragma unroll
                for (int n = 0; n < 4; ++n)
                    mma_bf16(acc[m][n], a[m], b[n].x, b[n].y);
        }

        // epilogue: bf16-round, store fp32 (c-frag: c0,c1 @ row l/4,
        // col 2(l%4); c2,c3 @ row+8)
        int orow = s * 64 + wm + (lane >> 2);
        int ocol = wn + 2 * (lane & 3);
#pragma unroll
        for (int m = 0; m < 2; ++m)
#pragma unroll
            for (int n = 0; n < 4; ++n) {
                float* c = acc[m][n];
#pragma unroll
                for (int t2 = 0; t2 < 4; ++t2)
                    c[t2] = __bfloat162float(__float2bfloat16(c[t2]));
                float* base = ob + (size_t)(orow + m * 16) * 128 + ocol + n * 8;
                *(float2*)base = make_float2(c[0], c[1]);
                *(float2*)(base + 8 * 128) = make_float2(c[2], c[3]);
            }

        // swap in stage 1
        if (s == 0) {
            __syncthreads();                // all warps done reading stage 0
            const float* xs = xb + 64 * 256;
#pragma unroll 4
            for (int j = 0; j < 16; ++j) {
                int u = tid + j * 256;
                int row = u >> 6, c4 = u & 63;
                float4 v = *(const float4*)(xs + (size_t)row * 256 + c4 * 4);
                *(uint2*)(smem + (size_t)row * AP_BYTES + c4 * 8) =
                    make_uint2(pack_bf(v.x, v.y), pack_bf(v.z, v.w));
            }
            __syncthreads();                // stage 1 visible
        }
    }
}

// -------------------------------------------------------------------- host ---
extern "C" void kernel_launch(void* const* d_in, const int* in_sizes, int n_in,
                              void* d_out, int out_size) {
    // identify inputs by element count (x=max, group_sizes=min, w=rest)
    int ix = 0, ig = 0;
    for (int i = 1; i < n_in; ++i) {
        if (in_sizes[i] > in_sizes[ix]) ix = i;
        if (in_sizes[i] < in_sizes[ig]) ig = i;
    }
    int iw = 0;
    for (int i = 0; i < n_in; ++i)
        if (i != ix && i != ig) { iw = i; break; }

    const float* x  = (const float*)d_in[ix];      // fp32 (bf16-valued)
    const float* w  = (const float*)d_in[iw];      // fp32 (bf16-valued)
    const int*   gs = (const int*)d_in[ig];
    float*      out = (float*)d_out;               // fp32 output

    int n_groups = in_sizes[ig];
    if (n_groups > 8) n_groups = 8;
    int n_tiles = in_sizes[ix] / (256 * 128);

    // 1) repack weights into fragment-major global (idempotent, in-graph)
    prep_w<<<(n_groups * 8192 + 255) / 256, 256>>>(w, n_groups);

    // 2) grouped GEMM
    cudaFuncSetAttribute(gg_kernel, cudaFuncAttributeMaxDynamicSharedMemorySize,
                         (int)SMEM_BYTES);
    gg_kernel<<<n_tiles, 256, SMEM_BYTES>>>(x, gs, out, n_groups);
}